// round 1
// baseline (speedup 1.0000x reference)
#include <cuda_runtime.h>
#include <math.h>

#define BB    8
#define CIN   256
#define RELC  32
#define OUTC  256
#define SHAREC 8
#define GG    32       // groups
#define MID   320      // 32 + 32*9
#define WOUT  288      // 9*32
#define HH    64
#define WWID  64
#define P     4096     // HH*WWID

// ---------------- scratch (static device arrays; no allocation) ----------------
__device__ float g_y[(size_t)BB * MID * P];     // conv1x1 outputs: [b][c][p], c: 0-31 x1, 32-63 x2, 64-319 x3
__device__ float g_t[(size_t)BB * GG * P];      // weight-gen hidden: [b][g][p]
__device__ float g_w[(size_t)BB * WOUT * P];    // per-pixel kernels: [b][g*9+k][p]
__device__ float g_Wc[MID * CIN];               // packed conv weights
__device__ float g_bias[MID];
__device__ float g_bn1s[MID];
__device__ float g_bn1b[MID];
__device__ float g_bn2s[GG];
__device__ float g_bn2b[GG];

// ---------------- K0: pack weights + fold BN params ----------------
__global__ void pack_kernel(const float* __restrict__ w1, const float* __restrict__ b1,
                            const float* __restrict__ w2, const float* __restrict__ b2,
                            const float* __restrict__ w3, const float* __restrict__ b3,
                            const float* __restrict__ bn1_g, const float* __restrict__ bn1_b,
                            const float* __restrict__ bn1_m, const float* __restrict__ bn1_v,
                            const float* __restrict__ bn2_g, const float* __restrict__ bn2_b,
                            const float* __restrict__ bn2_m, const float* __restrict__ bn2_v) {
    int c = blockIdx.x * blockDim.x + threadIdx.x;
    if (c >= MID) return;
    const float* src;
    float bv;
    if (c < 32)      { src = w1 + (size_t)c * CIN;        bv = b1[c]; }
    else if (c < 64) { src = w2 + (size_t)(c - 32) * CIN; bv = b2[c - 32]; }
    else             { src = w3 + (size_t)(c - 64) * CIN; bv = b3[c - 64]; }
    for (int k = 0; k < CIN; k++) g_Wc[c * CIN + k] = src[k];
    g_bias[c] = bv;
    float s = bn1_g[c] * rsqrtf(bn1_v[c] + 1e-5f);
    g_bn1s[c] = s;
    g_bn1b[c] = bn1_b[c] - bn1_m[c] * s;
    if (c < GG) {
        float s2 = bn2_g[c] * rsqrtf(bn2_v[c] + 1e-5f);
        g_bn2s[c] = s2;
        g_bn2b[c] = bn2_b[c] - bn2_m[c] * s2;
    }
}

// ---------------- K1: fused conv1x1 GEMM  y[b,m,p] = Wc[m,:] . x[b,:,p] + bias[m] ----------------
// Tiles: BM=64, BN=64, BK=16; 256 threads; 4x4 microtile per thread.
__global__ __launch_bounds__(256) void conv1x1_kernel(const float* __restrict__ x) {
    const int b  = blockIdx.z;
    const int m0 = blockIdx.y * 64;
    const int n0 = blockIdx.x * 64;
    __shared__ float As[16][64];   // As[k][m]
    __shared__ float Bs[16][64];   // Bs[k][n]

    const int tid = threadIdx.x;
    const int tx = tid & 15;       // col group
    const int ty = tid >> 4;       // row group
    const float* xb = x + (size_t)b * CIN * P;

    float acc[4][4];
#pragma unroll
    for (int i = 0; i < 4; i++)
#pragma unroll
        for (int j = 0; j < 4; j++) acc[i][j] = 0.f;

    for (int kk = 0; kk < CIN; kk += 16) {
        // A tile: 64 m x 16 k. Each thread loads float4 along k, transposes into As.
        {
            int m  = tid >> 2;
            int k4 = (tid & 3) * 4;
            float4 v = *(const float4*)&g_Wc[(m0 + m) * CIN + kk + k4];
            As[k4 + 0][m] = v.x; As[k4 + 1][m] = v.y;
            As[k4 + 2][m] = v.z; As[k4 + 3][m] = v.w;
        }
        // B tile: 16 k x 64 n, contiguous in n.
        {
            int k  = tid >> 4;
            int n4 = (tid & 15) * 4;
            *(float4*)&Bs[k][n4] = *(const float4*)&xb[(size_t)(kk + k) * P + n0 + n4];
        }
        __syncthreads();
#pragma unroll
        for (int k = 0; k < 16; k++) {
            float4 av = *(const float4*)&As[k][ty * 4];
            float4 bv = *(const float4*)&Bs[k][tx * 4];
            float a[4] = {av.x, av.y, av.z, av.w};
            float bq[4] = {bv.x, bv.y, bv.z, bv.w};
#pragma unroll
            for (int i = 0; i < 4; i++)
#pragma unroll
                for (int j = 0; j < 4; j++) acc[i][j] += a[i] * bq[j];
        }
        __syncthreads();
    }
#pragma unroll
    for (int i = 0; i < 4; i++) {
        int m = m0 + ty * 4 + i;
        float bv = g_bias[m];
        float* yrow = g_y + ((size_t)b * MID + m) * P + n0 + tx * 4;
#pragma unroll
        for (int j = 0; j < 4; j++) yrow[j] = acc[i][j] + bv;
    }
}

// ---------------- h(c,p): BN1+ReLU of [x1 ; unfold_reflect(x2)] computed on the fly ----------------
__device__ __forceinline__ float h_val(const float* __restrict__ yb, int c, int p) {
    float v;
    if (c < 32) {
        v = yb[(size_t)c * P + p];
    } else {
        int cc = c - 32;
        int r = cc / 9, k = cc - r * 9;
        int ki = k / 3 - 1, kj = k - (k / 3) * 3 - 1;
        int i = (p >> 6) + ki;
        int j = (p & 63) + kj;
        i = (i < 0) ? 1 : (i > 63 ? 62 : i);   // reflect pad (pad=1)
        j = (j < 0) ? 1 : (j > 63 ? 62 : j);
        v = yb[(size_t)(32 + r) * P + (i << 6) + j];
    }
    v = v * g_bn1s[c] + g_bn1b[c];
    return fmaxf(v, 0.f);
}

// ---------------- K3: t[b,g,p] = relu(bn2( cw1[g,:] . h[b,:,p] )) ----------------
// BM=32 (all groups), BN=128 pixels, BK=16; 256 threads; 4x4 microtile.
__global__ __launch_bounds__(256) void wgen1_kernel(const float* __restrict__ cw1) {
    const int b  = blockIdx.y;
    const int p0 = blockIdx.x * 128;
    __shared__ float As[16][32];    // As[k][g]
    __shared__ float Hs[16][128];   // Hs[k][n]
    const float* yb = g_y + (size_t)b * MID * P;
    const int tid = threadIdx.x;
    const int px = tid & 31;   // 32 column-groups of 4
    const int gy = tid >> 5;   // 8 row-groups

    float acc[4][4];
#pragma unroll
    for (int i = 0; i < 4; i++)
#pragma unroll
        for (int j = 0; j < 4; j++) acc[i][j] = 0.f;

    for (int kk = 0; kk < MID; kk += 16) {
#pragma unroll
        for (int e = 0; e < 2; e++) {
            int idx = tid + e * 256;
            int k = idx >> 5, g = idx & 31;
            As[k][g] = cw1[g * MID + kk + k];
        }
#pragma unroll
        for (int e = 0; e < 8; e++) {
            int idx = tid + e * 256;
            int k = idx >> 7, n = idx & 127;
            Hs[k][n] = h_val(yb, kk + k, p0 + n);
        }
        __syncthreads();
#pragma unroll
        for (int k = 0; k < 16; k++) {
            float a[4];
#pragma unroll
            for (int i = 0; i < 4; i++) a[i] = As[k][gy + i * 8];
            float4 hv = *(const float4*)&Hs[k][px * 4];
            float hb[4] = {hv.x, hv.y, hv.z, hv.w};
#pragma unroll
            for (int i = 0; i < 4; i++)
#pragma unroll
                for (int j = 0; j < 4; j++) acc[i][j] += a[i] * hb[j];
        }
        __syncthreads();
    }
#pragma unroll
    for (int i = 0; i < 4; i++) {
        int g = gy + i * 8;
        float s = g_bn2s[g], sh = g_bn2b[g];
        float* trow = g_t + ((size_t)b * GG + g) * P + p0 + px * 4;
#pragma unroll
        for (int j = 0; j < 4; j++) trow[j] = fmaxf(acc[i][j] * s + sh, 0.f);
    }
}

// ---------------- K4: w[b,o,p] = cw2[o,:] . t[b,:,p] + cb2[o] ----------------
// Block: 64 pixels, all 288 outputs; 256 threads = 4 o-quarters x 64 pixels.
__global__ __launch_bounds__(256) void wgen2_kernel(const float* __restrict__ cw2,
                                                    const float* __restrict__ cb2) {
    const int b  = blockIdx.y;
    const int p0 = blockIdx.x * 64;
    __shared__ float ts[GG][64];          // 8KB
    __shared__ float w2s[WOUT * GG];      // 36KB
    const int tid = threadIdx.x;

#pragma unroll
    for (int e = 0; e < 8; e++) {
        int idx = tid + e * 256;
        int g = idx >> 6, n = idx & 63;
        ts[g][n] = g_t[((size_t)b * GG + g) * P + p0 + n];
    }
    for (int idx = tid; idx < WOUT * GG; idx += 256) w2s[idx] = cw2[idx];
    __syncthreads();

    const int pp = tid & 63;
    const int q  = tid >> 6;    // 0..3, each handles 72 output channels
    float tv[GG];
#pragma unroll
    for (int g = 0; g < GG; g++) tv[g] = ts[g][pp];

    for (int o = q * 72; o < q * 72 + 72; o++) {
        float acc = cb2[o];
#pragma unroll
        for (int g = 0; g < GG; g++) acc += w2s[o * GG + g] * tv[g];
        g_w[((size_t)b * WOUT + o) * P + p0 + pp] = acc;
    }
}

// ---------------- K5: local grouped 3x3 conv (zero pad) ----------------
__global__ __launch_bounds__(256) void localconv_kernel(float* __restrict__ out) {
    const int bg = blockIdx.y;
    const int b = bg >> 5, g = bg & 31;
    const int p = blockIdx.x * 256 + threadIdx.x;
    const int i = p >> 6, j = p & 63;

    const float* wv = g_w + ((size_t)b * WOUT + g * 9) * P + p;
    float w[9];
#pragma unroll
    for (int k = 0; k < 9; k++) w[k] = wv[(size_t)k * P];

    const float* x3 = g_y + ((size_t)b * MID + 64 + g * SHAREC) * P;
    float* ob = out + ((size_t)b * OUTC + g * SHAREC) * P + p;

#pragma unroll
    for (int s = 0; s < SHAREC; s++) {
        const float* xc = x3 + (size_t)s * P;
        float acc = 0.f;
#pragma unroll
        for (int ki = 0; ki < 3; ki++) {
            int ii = i + ki - 1;
            if (ii < 0 || ii > 63) continue;
#pragma unroll
            for (int kj = 0; kj < 3; kj++) {
                int jj = j + kj - 1;
                if (jj < 0 || jj > 63) continue;
                acc += xc[(ii << 6) + jj] * w[ki * 3 + kj];
            }
        }
        ob[(size_t)s * P] = acc;
    }
}

// ---------------- launch ----------------
extern "C" void kernel_launch(void* const* d_in, const int* in_sizes, int n_in,
                              void* d_out, int out_size) {
    const float* x     = (const float*)d_in[0];
    const float* w1    = (const float*)d_in[1];
    const float* b1    = (const float*)d_in[2];
    const float* w2    = (const float*)d_in[3];
    const float* b2    = (const float*)d_in[4];
    const float* w3    = (const float*)d_in[5];
    const float* b3    = (const float*)d_in[6];
    const float* bn1_g = (const float*)d_in[7];
    const float* bn1_b = (const float*)d_in[8];
    const float* bn1_m = (const float*)d_in[9];
    const float* bn1_v = (const float*)d_in[10];
    const float* cw1   = (const float*)d_in[11];
    const float* bn2_g = (const float*)d_in[12];
    const float* bn2_b = (const float*)d_in[13];
    const float* bn2_m = (const float*)d_in[14];
    const float* bn2_v = (const float*)d_in[15];
    const float* cw2   = (const float*)d_in[16];
    const float* cb2   = (const float*)d_in[17];
    float* out = (float*)d_out;

    pack_kernel<<<5, 64>>>(w1, b1, w2, b2, w3, b3,
                           bn1_g, bn1_b, bn1_m, bn1_v,
                           bn2_g, bn2_b, bn2_m, bn2_v);

    {
        dim3 grid(P / 64, MID / 64, BB);   // 64 x 5 x 8
        conv1x1_kernel<<<grid, 256>>>(x);
    }
    {
        dim3 grid(P / 128, BB);            // 32 x 8
        wgen1_kernel<<<grid, 256>>>(cw1);
    }
    {
        dim3 grid(P / 64, BB);             // 64 x 8
        wgen2_kernel<<<grid, 256>>>(cw2, cb2);
    }
    {
        dim3 grid(P / 256, BB * GG);       // 16 x 256
        localconv_kernel<<<grid, 256>>>(out);
    }
}